// round 1
// baseline (speedup 1.0000x reference)
#include <cuda_runtime.h>
#include <math.h>

#define BATCH 64
#define NT    197
#define CH    768
#define NH    12
#define HD    64
#define BHN   (BATCH*NH)      // 768
#define ROWS  (BATCH*NT)      // 12608
#define QKN   (3*CH)          // 2304

// ---------------- scratch (static device arrays; no allocs allowed) ----------
__device__ float               g_q[(size_t)BHN*NT*HD];
__device__ float               g_k[(size_t)BHN*NT*HD];
__device__ float               g_v[(size_t)BHN*NT*HD];
__device__ unsigned long long  g_qb[BHN*NT];
__device__ unsigned long long  g_kb[BHN*NT];
__device__ float               g_sq[BHN];
__device__ float               g_sk[BHN];
__device__ float               g_vinv[BHN*HD];
__device__ signed char         g_v8[(size_t)BHN*NT*HD];
__device__ float               g_bias[NH*NT*NT];
__device__ float               g_ao[(size_t)ROWS*CH];

// ---------------- fp32 SGEMM: C = A * B^T (+bias), 128x128x16 tiles ----------
// MODE 0: A = x, B = w_qkv; epilogue scatters into g_q/g_k/g_v ([B,H,N,D])
// MODE 1: A = g_ao, B = w_proj; epilogue adds bias, writes Cout [ROWS,CH]
template<int MODE>
__global__ __launch_bounds__(256) void sgemm_k(const float* __restrict__ Ain,
                                               const float* __restrict__ Bw,
                                               const float* __restrict__ bias,
                                               float* __restrict__ Cout,
                                               int M, int Nn, int K)
{
    __shared__ float As[16][132];
    __shared__ float Bs[16][132];
    const float* A = (MODE == 1) ? (const float*)g_ao : Ain;

    int tid = threadIdx.x;
    int m0 = blockIdx.y * 128;
    int n0 = blockIdx.x * 128;

    int lr = tid >> 2;           // 0..63 (load row)
    int lc = (tid & 3) << 2;     // 0,4,8,12 (load k-col)
    int tr = tid >> 4;           // 0..15
    int tc = tid & 15;           // 0..15

    float acc[8][8];
#pragma unroll
    for (int i = 0; i < 8; i++)
#pragma unroll
        for (int j = 0; j < 8; j++) acc[i][j] = 0.f;

    for (int k0 = 0; k0 < K; k0 += 16) {
        int r0 = m0 + lr, r1 = m0 + lr + 64;
        float4 a0 = (r0 < M) ? *(const float4*)(A + (size_t)r0 * K + k0 + lc)
                             : make_float4(0.f, 0.f, 0.f, 0.f);
        float4 a1 = (r1 < M) ? *(const float4*)(A + (size_t)r1 * K + k0 + lc)
                             : make_float4(0.f, 0.f, 0.f, 0.f);
        float4 b0 = *(const float4*)(Bw + (size_t)(n0 + lr) * K + k0 + lc);
        float4 b1 = *(const float4*)(Bw + (size_t)(n0 + lr + 64) * K + k0 + lc);

        __syncthreads();
        As[lc + 0][lr] = a0.x; As[lc + 1][lr] = a0.y;
        As[lc + 2][lr] = a0.z; As[lc + 3][lr] = a0.w;
        As[lc + 0][lr + 64] = a1.x; As[lc + 1][lr + 64] = a1.y;
        As[lc + 2][lr + 64] = a1.z; As[lc + 3][lr + 64] = a1.w;
        Bs[lc + 0][lr] = b0.x; Bs[lc + 1][lr] = b0.y;
        Bs[lc + 2][lr] = b0.z; Bs[lc + 3][lr] = b0.w;
        Bs[lc + 0][lr + 64] = b1.x; Bs[lc + 1][lr + 64] = b1.y;
        Bs[lc + 2][lr + 64] = b1.z; Bs[lc + 3][lr + 64] = b1.w;
        __syncthreads();

#pragma unroll
        for (int kk = 0; kk < 16; kk++) {
            float4 x0 = *(const float4*)&As[kk][tr * 8];
            float4 x1 = *(const float4*)&As[kk][tr * 8 + 4];
            float4 y0 = *(const float4*)&Bs[kk][tc * 8];
            float4 y1 = *(const float4*)&Bs[kk][tc * 8 + 4];
            float av[8] = {x0.x, x0.y, x0.z, x0.w, x1.x, x1.y, x1.z, x1.w};
            float bv[8] = {y0.x, y0.y, y0.z, y0.w, y1.x, y1.y, y1.z, y1.w};
#pragma unroll
            for (int i = 0; i < 8; i++)
#pragma unroll
                for (int j = 0; j < 8; j++)
                    acc[i][j] = fmaf(av[i], bv[j], acc[i][j]);
        }
    }

    if (MODE == 0) {
#pragma unroll
        for (int i = 0; i < 8; i++) {
            int m = m0 + tr * 8 + i;
            if (m >= M) continue;
            int b = m / NT;
            int n = m - b * NT;
#pragma unroll
            for (int j = 0; j < 8; j++) {
                int cg = n0 + tc * 8 + j;           // 0..2303
                int which = cg / CH;                 // 0=q 1=k 2=v
                int rem = cg - which * CH;
                int h = rem >> 6;
                int d = rem & 63;
                size_t dst = (((size_t)(b * NH + h)) * NT + n) * HD + d;
                float* P = (which == 0) ? g_q : (which == 1) ? g_k : g_v;
                P[dst] = acc[i][j];
            }
        }
    } else {
#pragma unroll
        for (int i = 0; i < 8; i++) {
            int m = m0 + tr * 8 + i;
            if (m >= M) continue;
            float* crow = Cout + (size_t)m * Nn;
#pragma unroll
            for (int j = 0; j < 8; j++) {
                int cg = n0 + tc * 8 + j;
                crow[cg] = acc[i][j] + bias[cg];
            }
        }
    }
}

// -------- per-(b,h) stats: mean|q|,mean|k|, sign-bit packing, V int8 quant ---
__global__ __launch_bounds__(256) void stats_k()
{
    int bh = blockIdx.x;
    size_t base = (size_t)bh * NT * HD;
    const float* q = g_q + base;
    const float* k = g_k + base;
    const float* v = g_v + base;
    int tid = threadIdx.x, w = tid >> 5, l = tid & 31;

    __shared__ int   vmax[HD];
    __shared__ float svs[HD];
    __shared__ float r1[8], r2[8];
    if (tid < HD) vmax[tid] = 0;
    __syncthreads();

    float sa = 0.f, sb = 0.f;
    for (int i = tid; i < NT * HD; i += 256) {
        sa += fabsf(q[i]);
        sb += fabsf(k[i]);
        atomicMax(&vmax[i & 63], __float_as_int(fabsf(v[i])));
    }
#pragma unroll
    for (int o = 16; o; o >>= 1) {
        sa += __shfl_xor_sync(0xffffffffu, sa, o);
        sb += __shfl_xor_sync(0xffffffffu, sb, o);
    }
    if (l == 0) { r1[w] = sa; r2[w] = sb; }

    // sign-bit packing: warp per row, ballot over two half-rows
    for (int n = w; n < NT; n += 8) {
        float q0 = q[n * HD + l],      q1 = q[n * HD + 32 + l];
        float k0 = k[n * HD + l],      k1 = k[n * HD + 32 + l];
        unsigned bq0 = __ballot_sync(0xffffffffu, q0 < 0.f);
        unsigned bq1 = __ballot_sync(0xffffffffu, q1 < 0.f);
        unsigned bk0 = __ballot_sync(0xffffffffu, k0 < 0.f);
        unsigned bk1 = __ballot_sync(0xffffffffu, k1 < 0.f);
        if (l == 0) {
            g_qb[bh * NT + n] = (unsigned long long)bq0 | ((unsigned long long)bq1 << 32);
            g_kb[bh * NT + n] = (unsigned long long)bk0 | ((unsigned long long)bk1 << 32);
        }
    }
    __syncthreads();

    if (tid == 0) {
        float s1 = 0.f, s2 = 0.f;
        for (int i = 0; i < 8; i++) { s1 += r1[i]; s2 += r2[i]; }
        g_sq[bh] = s1 / (float)(NT * HD);
        g_sk[bh] = s2 / (float)(NT * HD);
    }
    if (tid < HD) {
        float m = __int_as_float(vmax[tid]);
        float s = 127.f / (m + 1e-6f);
        svs[tid] = s;
        g_vinv[bh * HD + tid] = 1.f / (s + 1e-6f);
    }
    __syncthreads();
    for (int i = tid; i < NT * HD; i += 256)
        g_v8[base + i] = (signed char)rintf(v[i] * svs[i & 63]);
}

// -------- relative-position bias gather: g_bias[h][n][m] ---------------------
__global__ __launch_bounds__(256) void bias_k(const float* __restrict__ rpb,
                                              const int* __restrict__ rel)
{
    int i = blockIdx.x * 256 + threadIdx.x;
    if (i < NH * NT * NT) {
        int h = i / (NT * NT);
        int r = i - h * (NT * NT);
        g_bias[i] = rpb[rel[r] * NH + h];
    }
}

// -------- fused attention: popcount logits -> softmax -> quant -> AV ---------
__global__ __launch_bounds__(256) void attn_k()
{
    extern __shared__ float sh[];
    float* sv = sh;                                           // NT*HD floats
    unsigned long long* skb = (unsigned long long*)(sv + NT * HD); // NT u64

    int bh = blockIdx.x;
    int b = bh / NH, h = bh - b * NH;
    size_t base = (size_t)bh * NT * HD;
    int tid = threadIdx.x, w = tid >> 5, l = tid & 31;

    for (int i = tid; i < NT * HD; i += 256) sv[i] = (float)g_v8[base + i];
    for (int i = tid; i < NT; i += 256) skb[i] = g_kb[bh * NT + i];
    __syncthreads();

    float p0 = g_sq[bh] * g_sk[bh];
    float fin0 = g_vinv[bh * HD + l]      * (1.0f / 255.0f);
    float fin1 = g_vinv[bh * HD + 32 + l] * (1.0f / 255.0f);
    const float* brow_base = g_bias + (size_t)h * NT * NT;

    for (int n = w; n < NT; n += 8) {
        unsigned long long qb = g_qb[bh * NT + n];
        const float* brow = brow_base + (size_t)n * NT;

        float lg[7];
        float mx = -3.0e38f;
#pragma unroll
        for (int j = 0; j < 7; j++) {
            int m = j * 32 + l;
            float val = -3.0e38f;
            if (m < NT) {
                int cnt = 64 - 2 * __popcll(qb ^ skb[m]);
                val = 0.125f * (p0 * (float)cnt) + brow[m];
            }
            lg[j] = val;
            mx = fmaxf(mx, val);
        }
#pragma unroll
        for (int o = 16; o; o >>= 1) mx = fmaxf(mx, __shfl_xor_sync(0xffffffffu, mx, o));

        float sum = 0.f;
#pragma unroll
        for (int j = 0; j < 7; j++) {
            float e = expf(lg[j] - mx);   // underflows to 0 for padding lanes
            lg[j] = e;
            sum += e;
        }
#pragma unroll
        for (int o = 16; o; o >>= 1) sum += __shfl_xor_sync(0xffffffffu, sum, o);

        float rs = 255.f / sum;
#pragma unroll
        for (int j = 0; j < 7; j++)
            lg[j] = fminf(rintf(lg[j] * rs), 255.f);   // integer prob in [0,255]

        float a0 = 0.f, a1 = 0.f;
#pragma unroll
        for (int j = 0; j < 6; j++) {
#pragma unroll
            for (int sl = 0; sl < 32; sl++) {
                float pm = __shfl_sync(0xffffffffu, lg[j], sl);
                int m = j * 32 + sl;
                a0 = fmaf(pm, sv[m * HD + l], a0);
                a1 = fmaf(pm, sv[m * HD + 32 + l], a1);
            }
        }
#pragma unroll
        for (int sl = 0; sl < 5; sl++) {
            float pm = __shfl_sync(0xffffffffu, lg[6], sl);
            int m = 192 + sl;
            a0 = fmaf(pm, sv[m * HD + l], a0);
            a1 = fmaf(pm, sv[m * HD + 32 + l], a1);
        }

        size_t ob = ((size_t)(b * NT + n)) * CH + h * HD;
        g_ao[ob + l]      = a0 * fin0;
        g_ao[ob + 32 + l] = a1 * fin1;
    }
}

// ---------------- launch ------------------------------------------------------
extern "C" void kernel_launch(void* const* d_in, const int* in_sizes, int n_in,
                              void* d_out, int out_size)
{
    const float* x     = (const float*)d_in[0];
    const float* wqkv  = (const float*)d_in[1];
    const float* wproj = (const float*)d_in[2];
    const float* bproj = (const float*)d_in[3];
    const float* rpb   = (const float*)d_in[4];
    const int*   rel   = (const int*)d_in[5];
    float* out = (float*)d_out;

    cudaFuncSetAttribute(attn_k, cudaFuncAttributeMaxDynamicSharedMemorySize, 64 * 1024);

    dim3 g1(QKN / 128, (ROWS + 127) / 128);
    sgemm_k<0><<<g1, 256>>>(x, wqkv, nullptr, nullptr, ROWS, QKN, CH);

    stats_k<<<BHN, 256>>>();
    bias_k<<<(NH * NT * NT + 255) / 256, 256>>>(rpb, rel);

    int attn_smem = NT * HD * 4 + NT * 8;   // 52008 bytes
    attn_k<<<BHN, 256, attn_smem>>>();

    dim3 g2(CH / 128, (ROWS + 127) / 128);
    sgemm_k<1><<<g2, 256>>>(nullptr, wproj, bproj, out, ROWS, CH, CH);
}

// round 5
// speedup vs baseline: 1.3722x; 1.3722x over previous
#include <cuda_runtime.h>
#include <cuda_fp16.h>
#include <math.h>
#include <stdint.h>

#define BATCH 64
#define NT    197
#define CH    768
#define NH    12
#define HD    64
#define BHN   (BATCH*NH)      // 768
#define ROWS  (BATCH*NT)      // 12608
#define QKN   (3*CH)          // 2304
#define KDIM  768
#define KC    64              // K per chunk
#define NCHUNK (KDIM/KC)      // 12
#define TILEB  (128*KC*2)     // 16384 bytes per tile (128 rows x 128B)
#define STAGEB (4*TILEB)      // 65536 per stage
#define DSMEM  (2*STAGEB + 128)

#define WSCALE   64.0f        // power-of-2 scale applied to both weight splits
#define AOSCALE  64.0f        // scale applied to attention-output split
#define INV_QKV  (1.0f/64.0f)     // x(1) * w(64)
#define INV_PROJ (1.0f/4096.0f)   // ao(64) * w(64)
#define QK_TAU   1.5e-3f      // |q| below this -> fp32 recompute (sign repair)

// ---------------- scratch (static device arrays; no allocs allowed) ----------
__device__ float               g_q[(size_t)BHN*NT*HD];
__device__ float               g_k[(size_t)BHN*NT*HD];
__device__ float               g_v[(size_t)BHN*NT*HD];
__device__ unsigned long long  g_qb[BHN*NT];
__device__ unsigned long long  g_kb[BHN*NT];
__device__ float               g_sq[BHN];
__device__ float               g_sk[BHN];
__device__ float               g_vinv[BHN*HD];
__device__ signed char         g_v8[(size_t)BHN*NT*HD];
__device__ float               g_bias[NH*NT*NT];
__device__ __align__(16) __half g_ah[(size_t)ROWS*CH];   // x-split, later ao-split
__device__ __align__(16) __half g_al[(size_t)ROWS*CH];
__device__ __align__(16) __half g_wh[(size_t)QKN*CH];
__device__ __align__(16) __half g_wl[(size_t)QKN*CH];
__device__ __align__(16) __half g_ph[(size_t)CH*CH];
__device__ __align__(16) __half g_pl[(size_t)CH*CH];

// ---------------- PTX helpers -------------------------------------------------
__device__ __forceinline__ uint32_t s2u(const void* p) {
    uint32_t r;
    asm("{ .reg .u64 t; cvta.to.shared.u64 t, %1; cvt.u32.u64 %0, t; }" : "=r"(r) : "l"(p));
    return r;
}
__device__ __forceinline__ void cp16(uint32_t saddr, const void* gaddr, uint32_t srcsize) {
    asm volatile("cp.async.cg.shared.global [%0], [%1], 16, %2;"
                 :: "r"(saddr), "l"(gaddr), "r"(srcsize) : "memory");
}
__device__ __forceinline__ void cp_commit() {
    asm volatile("cp.async.commit_group;" ::: "memory");
}
template<int N> __device__ __forceinline__ void cp_wait() {
    asm volatile("cp.async.wait_group %0;" :: "n"(N) : "memory");
}
__device__ __forceinline__ void ldsm4(uint32_t a, uint32_t& r0, uint32_t& r1,
                                      uint32_t& r2, uint32_t& r3) {
    asm volatile("ldmatrix.sync.aligned.m8n8.x4.shared.b16 {%0,%1,%2,%3}, [%4];"
                 : "=r"(r0), "=r"(r1), "=r"(r2), "=r"(r3) : "r"(a));
}
__device__ __forceinline__ void mma16816(float* c, const uint32_t* a,
                                         uint32_t b0, uint32_t b1) {
    asm volatile("mma.sync.aligned.m16n8k16.row.col.f32.f16.f16.f32 "
                 "{%0,%1,%2,%3}, {%4,%5,%6,%7}, {%8,%9}, {%0,%1,%2,%3};"
                 : "+f"(c[0]), "+f"(c[1]), "+f"(c[2]), "+f"(c[3])
                 : "r"(a[0]), "r"(a[1]), "r"(a[2]), "r"(a[3]), "r"(b0), "r"(b1));
}
__device__ __forceinline__ int dp4a_us(unsigned int a, int b, int c) {
    int d;
    asm("dp4a.u32.s32 %0, %1, %2, %3;" : "=r"(d) : "r"(a), "r"(b), "r"(c));
    return d;
}

// fp32 dot of x-row and w-row (768 elements), vectorized
__device__ __forceinline__ float dot768(const float* __restrict__ xr,
                                        const float* __restrict__ wr)
{
    const float4* a4 = (const float4*)xr;
    const float4* b4 = (const float4*)wr;
    float s0 = 0.f, s1 = 0.f, s2 = 0.f, s3 = 0.f;
#pragma unroll 4
    for (int i = 0; i < CH / 4; i++) {
        float4 a = a4[i], b = b4[i];
        s0 = fmaf(a.x, b.x, s0);
        s1 = fmaf(a.y, b.y, s1);
        s2 = fmaf(a.z, b.z, s2);
        s3 = fmaf(a.w, b.w, s3);
    }
    return (s0 + s1) + (s2 + s3);
}

// ---------------- fp16 hi/lo split with power-of-2 scale ----------------------
__device__ __forceinline__ void splith2(float x, float y, float s, uint32_t& h, uint32_t& l) {
    float xs = x * s, ys = y * s;
    __half hx = __float2half(xs), hy = __float2half(ys);
    __half lx = __float2half(xs - __half2float(hx));
    __half ly = __float2half(ys - __half2float(hy));
    h = (uint32_t)__half_as_ushort(hx) | ((uint32_t)__half_as_ushort(hy) << 16);
    l = (uint32_t)__half_as_ushort(lx) | ((uint32_t)__half_as_ushort(ly) << 16);
}
__global__ __launch_bounds__(256) void split8_k(const float* __restrict__ in,
                                                __half* __restrict__ hi,
                                                __half* __restrict__ lo,
                                                float s, int n8)
{
    int i = blockIdx.x * 256 + threadIdx.x;
    if (i >= n8) return;
    float4 a = ((const float4*)in)[i * 2];
    float4 b = ((const float4*)in)[i * 2 + 1];
    uint4 H, L;
    splith2(a.x, a.y, s, H.x, L.x);
    splith2(a.z, a.w, s, H.y, L.y);
    splith2(b.x, b.y, s, H.z, L.z);
    splith2(b.z, b.w, s, H.w, L.w);
    ((uint4*)hi)[i] = H;
    ((uint4*)lo)[i] = L;
}

// ---------------- mma.sync fp16x3 GEMM: C = A*B^T (fp32 emulation) -------------
template<int MODE>
__global__ __launch_bounds__(256)
void gemm_mma(const __half* __restrict__ Ah, const __half* __restrict__ Al,
              const __half* __restrict__ Bh, const __half* __restrict__ Bl,
              const float* __restrict__ bias, float* __restrict__ Cout, int M, int Nn)
{
    extern __shared__ char dyn[];
    uint32_t dbase = s2u(dyn);
    uint32_t pad = (128u - (dbase & 127u)) & 127u;
    uint32_t S = dbase + pad;

    int t = threadIdx.x;
    int wid = t >> 5, l = t & 31;
    int m0 = blockIdx.y * 128;
    int n0 = blockIdx.x * 128;

    int ldr = t >> 3, ldc = t & 7;

    int r8 = l & 7, mi = l >> 3;
    int rsel = ((mi & 1) << 3) + r8;
    int hm = mi >> 1;
    int wm = (wid >> 2) * 64;
    int wn = (wid & 3) * 32;

    uint32_t apart[4]; int ax[4];
#pragma unroll
    for (int i = 0; i < 4; i++) {
        int row = wm + i * 16 + rsel;
        apart[i] = (uint32_t)(row * 128);
        ax[i] = row & 7;
    }
    uint32_t bpart[2]; int bx[2];
#pragma unroll
    for (int jj = 0; jj < 2; jj++) {
        int row = wn + jj * 16 + rsel;
        bpart[jj] = (uint32_t)(row * 128);
        bx[jj] = row & 7;
    }

    float acc[4][4][4];
#pragma unroll
    for (int i = 0; i < 4; i++)
#pragma unroll
        for (int j = 0; j < 4; j++)
#pragma unroll
            for (int e = 0; e < 4; e++) acc[i][j][e] = 0.f;

    const __half* Asrc[2] = {Ah, Al};
    const __half* Bsrc[2] = {Bh, Bl};

    auto load_stage = [&](int c) {
        uint32_t st = S + (uint32_t)(c & 1) * STAGEB;
        int k0 = c * KC;
#pragma unroll
        for (int ti = 0; ti < 2; ti++) {
#pragma unroll
            for (int i = 0; i < 4; i++) {
                int rr = ldr + i * 32;
                int grow = m0 + rr;
                uint32_t ss = st + (uint32_t)ti * TILEB + (uint32_t)(rr * 128)
                              + (uint32_t)(((ldc ^ (rr & 7))) << 4);
                const void* g = (const char*)Asrc[ti]
                              + (((size_t)grow * KDIM + k0 + ldc * 8) * 2);
                cp16(ss, g, (grow < M) ? 16u : 0u);
            }
        }
#pragma unroll
        for (int ti = 0; ti < 2; ti++) {
#pragma unroll
            for (int i = 0; i < 4; i++) {
                int rr = ldr + i * 32;
                uint32_t ss = st + (uint32_t)(2 + ti) * TILEB + (uint32_t)(rr * 128)
                              + (uint32_t)(((ldc ^ (rr & 7))) << 4);
                const void* g = (const char*)Bsrc[ti]
                              + (((size_t)(n0 + rr) * KDIM + k0 + ldc * 8) * 2);
                cp16(ss, g, 16u);
            }
        }
        cp_commit();
    };

    load_stage(0);

    for (int c = 0; c < NCHUNK; c++) {
        if (c + 1 < NCHUNK) { load_stage(c + 1); cp_wait<1>(); }
        else                { cp_wait<0>(); }
        __syncthreads();

        uint32_t st = S + (uint32_t)(c & 1) * STAGEB;
#pragma unroll
        for (int pass = 0; pass < 3; pass++) {
            uint32_t aT = st + (uint32_t)((pass == 2) ? 1 : 0) * TILEB;
            uint32_t bT = st + (uint32_t)((pass == 1) ? 3 : 2) * TILEB;
#pragma unroll
            for (int ks = 0; ks < 4; ks++) {
                int cbase = ks * 2 + hm;
                uint32_t a[4][4];
#pragma unroll
                for (int i = 0; i < 4; i++)
                    ldsm4(aT + apart[i] + (uint32_t)((cbase ^ ax[i]) << 4),
                          a[i][0], a[i][1], a[i][2], a[i][3]);
                uint32_t bb[2][4];
#pragma unroll
                for (int jj = 0; jj < 2; jj++)
                    ldsm4(bT + bpart[jj] + (uint32_t)((cbase ^ bx[jj]) << 4),
                          bb[jj][0], bb[jj][1], bb[jj][2], bb[jj][3]);
#pragma unroll
                for (int i = 0; i < 4; i++) {
                    mma16816(acc[i][0], a[i], bb[0][0], bb[0][2]);
                    mma16816(acc[i][1], a[i], bb[0][1], bb[0][3]);
                    mma16816(acc[i][2], a[i], bb[1][0], bb[1][2]);
                    mma16816(acc[i][3], a[i], bb[1][1], bb[1][3]);
                }
            }
        }
        __syncthreads();
    }

    int gID = l >> 2, tig = l & 3;
    if (MODE == 0) {
        int which = n0 / CH;
        float* P = (which == 0) ? g_q : (which == 1) ? g_k : g_v;
        int rem0 = n0 - which * CH;
#pragma unroll
        for (int i = 0; i < 4; i++) {
#pragma unroll
            for (int half = 0; half < 2; half++) {
                int m = m0 + wm + i * 16 + gID + half * 8;
                if (m >= M) continue;
                int b = m / NT, n = m - b * NT;
#pragma unroll
                for (int j = 0; j < 4; j++) {
                    int rem = rem0 + wn + j * 8 + tig * 2;
                    int h = rem >> 6, d = rem & 63;
                    float2 v2 = half
                        ? make_float2(acc[i][j][2] * INV_QKV, acc[i][j][3] * INV_QKV)
                        : make_float2(acc[i][j][0] * INV_QKV, acc[i][j][1] * INV_QKV);
                    *(float2*)&P[(((size_t)(b * NH + h)) * NT + n) * HD + d] = v2;
                }
            }
        }
    } else {
#pragma unroll
        for (int i = 0; i < 4; i++) {
#pragma unroll
            for (int half = 0; half < 2; half++) {
                int m = m0 + wm + i * 16 + gID + half * 8;
                if (m >= M) continue;
                float* crow = Cout + (size_t)m * CH;
#pragma unroll
                for (int j = 0; j < 4; j++) {
                    int cg = n0 + wn + j * 8 + tig * 2;
                    float2 bb2 = *(const float2*)&bias[cg];
                    float2 v2 = half
                        ? make_float2(acc[i][j][2] * INV_PROJ + bb2.x, acc[i][j][3] * INV_PROJ + bb2.y)
                        : make_float2(acc[i][j][0] * INV_PROJ + bb2.x, acc[i][j][1] * INV_PROJ + bb2.y);
                    *(float2*)&crow[cg] = v2;
                }
            }
        }
    }
}

// -------- fp32 sign repair: recompute near-zero q/k elements exactly ----------
__global__ __launch_bounds__(256) void repair_qk(const float* __restrict__ x,
                                                 const float* __restrict__ w)
{
    int idx = blockIdx.x * 256 + threadIdx.x;
    const int PER = BHN * NT * HD;
    if (idx >= 2 * PER) return;
    int t = idx >= PER;
    int r = idx - t * PER;
    float* P = t ? g_k : g_q;
    float val = P[r];
    if (fabsf(val) >= QK_TAU) return;
    int d = r & 63;
    int n = (r >> 6) % NT;
    int bh = r / (NT * HD);
    int b = bh / NH, h = bh - b * NH;
    const float* xr = x + (size_t)(b * NT + n) * CH;
    const float* wr = w + (size_t)(t * CH + h * HD + d) * CH;
    P[r] = dot768(xr, wr);
}

// -------- per-(b,h) stats + v int8 quant with fp32 boundary repair ------------
__global__ __launch_bounds__(256) void stats_k(const float* __restrict__ x,
                                               const float* __restrict__ wqkv)
{
    int bh = blockIdx.x;
    size_t base = (size_t)bh * NT * HD;
    const float* q = g_q + base;
    const float* k = g_k + base;
    const float* v = g_v + base;
    int tid = threadIdx.x, w = tid >> 5, l = tid & 31;
    int b = bh / NH, hh = bh - b * NH;

    __shared__ int   vmax[HD];
    __shared__ float svs[HD];
    __shared__ float r1[8], r2[8];
    if (tid < HD) vmax[tid] = 0;
    __syncthreads();

    float sa = 0.f, sb = 0.f;
    for (int i = tid; i < NT * HD; i += 256) {
        sa += fabsf(q[i]);
        sb += fabsf(k[i]);
        atomicMax(&vmax[i & 63], __float_as_int(fabsf(v[i])));
    }
#pragma unroll
    for (int o = 16; o; o >>= 1) {
        sa += __shfl_xor_sync(0xffffffffu, sa, o);
        sb += __shfl_xor_sync(0xffffffffu, sb, o);
    }
    if (l == 0) { r1[w] = sa; r2[w] = sb; }

    for (int n = w; n < NT; n += 8) {
        float q0 = q[n * HD + l],      q1 = q[n * HD + 32 + l];
        float k0 = k[n * HD + l],      k1 = k[n * HD + 32 + l];
        unsigned bq0 = __ballot_sync(0xffffffffu, q0 < 0.f);
        unsigned bq1 = __ballot_sync(0xffffffffu, q1 < 0.f);
        unsigned bk0 = __ballot_sync(0xffffffffu, k0 < 0.f);
        unsigned bk1 = __ballot_sync(0xffffffffu, k1 < 0.f);
        if (l == 0) {
            g_qb[bh * NT + n] = (unsigned long long)bq0 | ((unsigned long long)bq1 << 32);
            g_kb[bh * NT + n] = (unsigned long long)bk0 | ((unsigned long long)bk1 << 32);
        }
    }
    __syncthreads();

    if (tid == 0) {
        float s1 = 0.f, s2 = 0.f;
        for (int i = 0; i < 8; i++) { s1 += r1[i]; s2 += r2[i]; }
        g_sq[bh] = s1 / (float)(NT * HD);
        g_sk[bh] = s2 / (float)(NT * HD);
    }
    if (tid < HD) {
        float mm = __int_as_float(vmax[tid]);
        float s = 127.f / (mm + 1e-6f);
        svs[tid] = s;
        g_vinv[bh * HD + tid] = 1.f / (s + 1e-6f);
    }
    __syncthreads();
    for (int i = tid; i < NT * HD; i += 256) {
        float vv = v[i];
        int d = i & 63;
        float tq = vv * svs[d];
        if (fabsf(tq - rintf(tq)) > 0.498f) {
            // near a rounding boundary: recompute v in fp32 to settle the LSB
            int n = i >> 6;
            const float* xr = x + (size_t)(b * NT + n) * CH;
            const float* wr = wqkv + (size_t)(2 * CH + hh * HD + d) * CH;
            vv = dot768(xr, wr);
            tq = vv * svs[d];
        }
        g_v8[base + i] = (signed char)rintf(tq);
    }
}

// -------- relative-position bias gather: g_bias[h][n][m] ---------------------
__global__ __launch_bounds__(256) void bias_k(const float* __restrict__ rpb,
                                              const int* __restrict__ rel)
{
    int i = blockIdx.x * 256 + threadIdx.x;
    if (i < NH * NT * NT) {
        int h = i / (NT * NT);
        int r = i - h * (NT * NT);
        g_bias[i] = rpb[rel[r] * NH + h];
    }
}

// -------- fused attention: popcount logits -> softmax -> quant -> dp4a AV ----
#define VROW 204
__global__ __launch_bounds__(256) void attn_k()
{
    __shared__ unsigned long long skb[NT];
    __shared__ signed char  svt[HD * VROW];
    __shared__ unsigned char pbuf[8 * VROW];

    int bh = blockIdx.x;
    int b = bh / NH, h = bh - b * NH;
    size_t base = (size_t)bh * NT * HD;
    int tid = threadIdx.x, w = tid >> 5, l = tid & 31;

    for (int i = tid; i < 8 * VROW / 4; i += 256) ((uint32_t*)pbuf)[i] = 0u;
    for (int i = tid; i < NT * HD; i += 256) {
        int n = i >> 6, d = i & 63;
        svt[d * VROW + n] = g_v8[base + i];
    }
    for (int i = tid; i < NT; i += 256) skb[i] = g_kb[bh * NT + i];
    __syncthreads();

    float p0 = g_sq[bh] * g_sk[bh];
    float fin0 = g_vinv[bh * HD + l]      * (1.0f / 255.0f);
    float fin1 = g_vinv[bh * HD + 32 + l] * (1.0f / 255.0f);
    const float* brow_base = g_bias + (size_t)h * NT * NT;
    unsigned char* pw = pbuf + w * VROW;
    const int* prow = (const int*)pw;
    const int* sv0 = (const int*)(svt + (size_t)l * VROW);
    const int* sv1 = (const int*)(svt + (size_t)(l + 32) * VROW);

    for (int n = w; n < NT; n += 8) {
        unsigned long long qb = g_qb[bh * NT + n];
        const float* brow = brow_base + (size_t)n * NT;

        float lg[7];
        float mx = -3.0e38f;
#pragma unroll
        for (int j = 0; j < 7; j++) {
            int m = j * 32 + l;
            float val = -3.0e38f;
            if (m < NT) {
                int cnt = 64 - 2 * __popcll(qb ^ skb[m]);
                val = 0.125f * (p0 * (float)cnt) + brow[m];
            }
            lg[j] = val;
            mx = fmaxf(mx, val);
        }
#pragma unroll
        for (int o = 16; o; o >>= 1) mx = fmaxf(mx, __shfl_xor_sync(0xffffffffu, mx, o));

        float sum = 0.f;
#pragma unroll
        for (int j = 0; j < 7; j++) {
            float e = expf(lg[j] - mx);
            lg[j] = e;
            sum += e;
        }
#pragma unroll
        for (int o = 16; o; o >>= 1) sum += __shfl_xor_sync(0xffffffffu, sum, o);

        float rs = 255.f / sum;
        __syncwarp();
#pragma unroll
        for (int j = 0; j < 7; j++) {
            int m = j * 32 + l;
            if (m < NT)
                pw[m] = (unsigned char)(int)fminf(rintf(lg[j] * rs), 255.f);
        }
        __syncwarp();

        int ia0 = 0, ia1 = 0;
#pragma unroll
        for (int g = 0; g < VROW / 4; g++) {
            int pv = prow[g];
            ia0 = dp4a_us((unsigned)pv, sv0[g], ia0);
            ia1 = dp4a_us((unsigned)pv, sv1[g], ia1);
        }

        float o0 = (float)ia0 * fin0 * AOSCALE;
        float o1 = (float)ia1 * fin1 * AOSCALE;
        size_t ob = ((size_t)(b * NT + n)) * CH + h * HD;
        __half h0 = __float2half(o0);
        __half h1 = __float2half(o1);
        g_ah[ob + l]      = h0;
        g_al[ob + l]      = __float2half(o0 - __half2float(h0));
        g_ah[ob + 32 + l] = h1;
        g_al[ob + 32 + l] = __float2half(o1 - __half2float(h1));
    }
}

// ---------------- launch ------------------------------------------------------
extern "C" void kernel_launch(void* const* d_in, const int* in_sizes, int n_in,
                              void* d_out, int out_size)
{
    const float* x     = (const float*)d_in[0];
    const float* wqkv  = (const float*)d_in[1];
    const float* wproj = (const float*)d_in[2];
    const float* bproj = (const float*)d_in[3];
    const float* rpb   = (const float*)d_in[4];
    const int*   rel   = (const int*)d_in[5];
    float* out = (float*)d_out;

    void *p_ah, *p_al, *p_wh, *p_wl, *p_ph, *p_pl;
    cudaGetSymbolAddress(&p_ah, g_ah);
    cudaGetSymbolAddress(&p_al, g_al);
    cudaGetSymbolAddress(&p_wh, g_wh);
    cudaGetSymbolAddress(&p_wl, g_wl);
    cudaGetSymbolAddress(&p_ph, g_ph);
    cudaGetSymbolAddress(&p_pl, g_pl);

    cudaFuncSetAttribute(gemm_mma<0>, cudaFuncAttributeMaxDynamicSharedMemorySize, DSMEM);
    cudaFuncSetAttribute(gemm_mma<1>, cudaFuncAttributeMaxDynamicSharedMemorySize, DSMEM);

    int n8x = ROWS * CH / 8;
    int n8w = QKN * CH / 8;
    int n8p = CH * CH / 8;
    split8_k<<<(n8x + 255) / 256, 256>>>(x, (__half*)p_ah, (__half*)p_al, 1.0f, n8x);
    split8_k<<<(n8w + 255) / 256, 256>>>(wqkv, (__half*)p_wh, (__half*)p_wl, WSCALE, n8w);
    split8_k<<<(n8p + 255) / 256, 256>>>(wproj, (__half*)p_ph, (__half*)p_pl, WSCALE, n8p);

    gemm_mma<0><<<dim3(QKN / 128, (ROWS + 127) / 128), 256, DSMEM>>>(
        (const __half*)p_ah, (const __half*)p_al,
        (const __half*)p_wh, (const __half*)p_wl,
        nullptr, nullptr, ROWS, QKN);

    int nrep = 2 * BHN * NT * HD;
    repair_qk<<<(nrep + 255) / 256, 256>>>(x, wqkv);

    stats_k<<<BHN, 256>>>(x, wqkv);
    bias_k<<<(NH * NT * NT + 255) / 256, 256>>>(rpb, rel);

    attn_k<<<BHN, 256>>>();

    gemm_mma<1><<<dim3(CH / 128, (ROWS + 127) / 128), 256, DSMEM>>>(
        (const __half*)p_ah, (const __half*)p_al,
        (const __half*)p_ph, (const __half*)p_pl,
        bproj, out, ROWS, CH);
}